// round 5
// baseline (speedup 1.0000x reference)
#include <cuda_runtime.h>

// ---------------------------------------------------------------------------
// SimpleAttention: qkv 1x1 conv+BN -> per-head transposed attention ->
//                  + depthwise 3x3 conv+BN(v) -> proj 1x1 conv+BN
// B=8, Hs=Ws=32 (N=1024), C=256, heads=8, key_dim=16, head_dim=32
// ---------------------------------------------------------------------------

#define BATCH 8
#define NSP   1024          // tokens per image (32*32)
#define CDIM  256
#define HQKV  512
#define NH    8
#define KDIM  16
#define HD    32
#define NHEADS_TOT 64       // BATCH*NH
#define MTOT  8192          // BATCH*NSP
#define ATT_SCALE 0.25f     // 16^-0.5
#define BN_EPS 0.001f

// ------------------------------- scratch ----------------------------------
__device__ __align__(16) float g_Q [NHEADS_TOT * NSP * KDIM];   // (b,h,n,k)
__device__ __align__(16) float g_Kt[NHEADS_TOT * NSP * KDIM];   // (b,h,m,k)
__device__ __align__(16) float g_V [MTOT * CDIM];               // v_img (b,n, h*32+d)
__device__ __align__(16) float g_P [(size_t)NHEADS_TOT * NSP * NSP]; // softmax probs (head,n,m)
__device__ __align__(16) float g_X [MTOT * CDIM];               // attn-out image + pe
__device__ float g_sqkv[HQKV], g_bqkv[HQKV];
__device__ float g_spe [CDIM], g_bpe [CDIM];
__device__ float g_sprj[CDIM], g_bprj[CDIM];

// -------------------------- BN fold (tiny) ---------------------------------
__global__ void bn_prep(const float* __restrict__ qg, const float* __restrict__ qb,
                        const float* __restrict__ qm, const float* __restrict__ qv,
                        const float* __restrict__ pg, const float* __restrict__ pb,
                        const float* __restrict__ pm, const float* __restrict__ pv,
                        const float* __restrict__ rg, const float* __restrict__ rb,
                        const float* __restrict__ rm, const float* __restrict__ rv) {
    int i = threadIdx.x;
    if (i < HQKV) {
        float s = qg[i] * rsqrtf(qv[i] + BN_EPS);
        g_sqkv[i] = s; g_bqkv[i] = qb[i] - qm[i] * s;
    }
    if (i < CDIM) {
        float s = pg[i] * rsqrtf(pv[i] + BN_EPS);
        g_spe[i] = s; g_bpe[i] = pb[i] - pm[i] * s;
        float s2 = rg[i] * rsqrtf(rv[i] + BN_EPS);
        g_sprj[i] = s2; g_bprj[i] = rb[i] - rm[i] * s2;
    }
}

// ---------------- GEMM 1: QKV = X(8192x256) @ W(256x512), BN, scatter ------
__global__ __launch_bounds__(256)
void qkv_gemm(const float* __restrict__ A, const float* __restrict__ W) {
    __shared__ float As[16][64];
    __shared__ float Bs[16][64];
    int tx = threadIdx.x, ty = threadIdx.y;
    int tid = ty * 16 + tx;
    int m0 = blockIdx.y * 64, n0 = blockIdx.x * 64;

    float acc[4][4] = {};
    int arow = tid >> 2, akq = (tid & 3) * 4;     // A-tile loader mapping
    int brow = tid >> 4, bcol = (tid & 15) * 4;   // B-tile loader mapping

    for (int k0 = 0; k0 < CDIM; k0 += 16) {
        float4 a4 = *(const float4*)&A[(size_t)(m0 + arow) * CDIM + k0 + akq];
        As[akq + 0][arow] = a4.x; As[akq + 1][arow] = a4.y;
        As[akq + 2][arow] = a4.z; As[akq + 3][arow] = a4.w;
        *(float4*)&Bs[brow][bcol] =
            *(const float4*)&W[(size_t)(k0 + brow) * HQKV + n0 + bcol];
        __syncthreads();
        #pragma unroll
        for (int kk = 0; kk < 16; kk++) {
            float4 av = *(float4*)&As[kk][ty * 4];
            float4 bv = *(float4*)&Bs[kk][tx * 4];
            float a[4] = {av.x, av.y, av.z, av.w};
            float b[4] = {bv.x, bv.y, bv.z, bv.w};
            #pragma unroll
            for (int i = 0; i < 4; i++)
                #pragma unroll
                for (int j = 0; j < 4; j++)
                    acc[i][j] = fmaf(a[i], b[j], acc[i][j]);
        }
        __syncthreads();
    }

    #pragma unroll
    for (int i = 0; i < 4; i++) {
        int gm = m0 + ty * 4 + i;
        int bb = gm >> 10, n = gm & 1023;
        #pragma unroll
        for (int j = 0; j < 4; j++) {
            int gn = n0 + tx * 4 + j;
            float v = fmaf(acc[i][j], g_sqkv[gn], g_bqkv[gn]);
            int h = gn >> 6, r = gn & 63;
            if (r < KDIM)
                g_Q[((bb * NH + h) * NSP + n) * KDIM + r] = v;
            else if (r < 2 * KDIM)
                g_Kt[((bb * NH + h) * NSP + n) * KDIM + (r - KDIM)] = v;
            else
                g_V[(size_t)gm * CDIM + h * HD + (r - 2 * KDIM)] = v;
        }
    }
}

// ---------------- Attention scores + softmax -> g_P ------------------------
// One block = 32 rows of one head. K kept in SMEM (stride-20 rows: bank-free).
// Each warp processes 2 rows concurrently (halves LDS traffic) x 2 passes.
#define KROW 20
__device__ __forceinline__ float dot16(float4 q0, float4 q1, float4 q2, float4 q3,
                                       const float* kp) {
    float4 k0 = *(const float4*)&kp[0];
    float4 k1 = *(const float4*)&kp[4];
    float4 k2 = *(const float4*)&kp[8];
    float4 k3 = *(const float4*)&kp[12];
    float d = q0.x * k0.x;
    d = fmaf(q0.y, k0.y, d); d = fmaf(q0.z, k0.z, d); d = fmaf(q0.w, k0.w, d);
    d = fmaf(q1.x, k1.x, d); d = fmaf(q1.y, k1.y, d); d = fmaf(q1.z, k1.z, d);
    d = fmaf(q1.w, k1.w, d); d = fmaf(q2.x, k2.x, d); d = fmaf(q2.y, k2.y, d);
    d = fmaf(q2.z, k2.z, d); d = fmaf(q2.w, k2.w, d); d = fmaf(q3.x, k3.x, d);
    d = fmaf(q3.y, k3.y, d); d = fmaf(q3.z, k3.z, d); d = fmaf(q3.w, k3.w, d);
    return d;
}

__global__ __launch_bounds__(256)
void attn_softmax() {
    extern __shared__ float Ks[];                 // [1024][KROW]
    int head = blockIdx.y;
    int tid = threadIdx.x;

    const float4* Kg = (const float4*)(g_Kt + (size_t)head * NSP * KDIM);
    for (int idx = tid; idx < NSP * 4; idx += 256) {
        int m = idx >> 2, q = idx & 3;
        *(float4*)&Ks[m * KROW + q * 4] = Kg[idx];
    }
    __syncthreads();

    int warp = tid >> 5, lane = tid & 31;
    #pragma unroll
    for (int pair = 0; pair < 2; pair++) {
        int rowA = blockIdx.x * 32 + warp * 4 + pair * 2;
        int rowB = rowA + 1;
        const float* qa = g_Q + ((size_t)head * NSP + rowA) * KDIM;
        const float* qb = g_Q + ((size_t)head * NSP + rowB) * KDIM;
        float4 qa0 = *(const float4*)&qa[0], qa1 = *(const float4*)&qa[4];
        float4 qa2 = *(const float4*)&qa[8], qa3 = *(const float4*)&qa[12];
        float4 qb0 = *(const float4*)&qb[0], qb1 = *(const float4*)&qb[4];
        float4 qb2 = *(const float4*)&qb[8], qb3 = *(const float4*)&qb[12];

        float sA[32], sB[32];
        float mxA = -1e30f, mxB = -1e30f;
        #pragma unroll
        for (int i = 0; i < 32; i++) {
            int m = i * 32 + lane;
            const float* kp = &Ks[m * KROW];
            float dA = dot16(qa0, qa1, qa2, qa3, kp);
            float dB = dot16(qb0, qb1, qb2, qb3, kp);
            sA[i] = dA * ATT_SCALE; sB[i] = dB * ATT_SCALE;
            mxA = fmaxf(mxA, sA[i]); mxB = fmaxf(mxB, sB[i]);
        }
        #pragma unroll
        for (int o = 16; o > 0; o >>= 1) {
            mxA = fmaxf(mxA, __shfl_xor_sync(0xffffffffu, mxA, o));
            mxB = fmaxf(mxB, __shfl_xor_sync(0xffffffffu, mxB, o));
        }
        float sumA = 0.f, sumB = 0.f;
        #pragma unroll
        for (int i = 0; i < 32; i++) {
            sA[i] = __expf(sA[i] - mxA); sumA += sA[i];
            sB[i] = __expf(sB[i] - mxB); sumB += sB[i];
        }
        #pragma unroll
        for (int o = 16; o > 0; o >>= 1) {
            sumA += __shfl_xor_sync(0xffffffffu, sumA, o);
            sumB += __shfl_xor_sync(0xffffffffu, sumB, o);
        }
        float invA = 1.f / sumA, invB = 1.f / sumB;
        float* PrA = g_P + (size_t)head * NSP * NSP + (size_t)rowA * NSP;
        float* PrB = g_P + (size_t)head * NSP * NSP + (size_t)rowB * NSP;
        #pragma unroll
        for (int i = 0; i < 32; i++) {
            PrA[i * 32 + lane] = sA[i] * invA;
            PrB[i * 32 + lane] = sB[i] * invB;
        }
    }
}

// ---------------- out[m,d] = sum_n P[n,m] * V[n,d]  -> g_X (reshaped) ------
// Per head: M=1024 (m), N=32 (d), K=1024 (n). Block = 128 m x 32 d.
__global__ __launch_bounds__(256)
void av_gemm() {
    __shared__ float Ps[32][128];
    __shared__ float Vs[32][32];
    int head = blockIdx.y;
    int bb = head >> 3, h = head & 7;
    int m0 = blockIdx.x * 128;
    int tx = threadIdx.x;          // 0..31 (m groups)
    int ty = threadIdx.y;          // 0..7  (d groups)
    int tid = ty * 32 + tx;

    const float* Pbase = g_P + (size_t)head * NSP * NSP;
    const float* Vbase = g_V + (size_t)bb * NSP * CDIM + h * HD;

    float acc[4][4] = {};
    int pr = tid >> 3, pf = tid & 7;

    for (int n0 = 0; n0 < NSP; n0 += 32) {
        #pragma unroll
        for (int j = 0; j < 4; j++)
            *(float4*)&Ps[pr][(pf + j * 8) * 4] =
                *(const float4*)&Pbase[(size_t)(n0 + pr) * NSP + m0 + (pf + j * 8) * 4];
        *(float4*)&Vs[pr][pf * 4] =
            *(const float4*)&Vbase[(size_t)(n0 + pr) * CDIM + pf * 4];
        __syncthreads();
        #pragma unroll
        for (int kk = 0; kk < 32; kk++) {
            float4 av = *(float4*)&Ps[kk][tx * 4];
            float4 bv = *(float4*)&Vs[kk][ty * 4];
            float a[4] = {av.x, av.y, av.z, av.w};
            float b[4] = {bv.x, bv.y, bv.z, bv.w};
            #pragma unroll
            for (int i = 0; i < 4; i++)
                #pragma unroll
                for (int j = 0; j < 4; j++)
                    acc[i][j] = fmaf(a[i], b[j], acc[i][j]);
        }
        __syncthreads();
    }

    // x_img[b, hs=d, ws=h*4+m/256, c=m%256] = out[m,d]
    #pragma unroll
    for (int i = 0; i < 4; i++) {
        int m = m0 + tx * 4 + i;
        int ws = h * 4 + (m >> 8);
        int c = m & 255;
        #pragma unroll
        for (int j = 0; j < 4; j++) {
            int d = ty * 4 + j;
            g_X[((size_t)(bb * 32 + d) * 32 + ws) * 256 + c] = acc[i][j];
        }
    }
}

// ---------------- depthwise 3x3 conv on v_img + BN, accumulate into g_X ----
__global__ __launch_bounds__(256)
void pe_add(const float* __restrict__ pw) {
    int idx = blockIdx.x * 256 + threadIdx.x;   // over MTOT*CDIM
    int c  = idx & 255;
    int ws = (idx >> 8) & 31;
    int hs = (idx >> 13) & 31;
    int bb = idx >> 18;
    float accum = 0.f;
    #pragma unroll
    for (int dy = 0; dy < 3; dy++) {
        int y = hs + dy - 1;
        if ((unsigned)y >= 32u) continue;
        #pragma unroll
        for (int dx = 0; dx < 3; dx++) {
            int x = ws + dx - 1;
            if ((unsigned)x >= 32u) continue;
            accum = fmaf(pw[(dy * 3 + dx) * 256 + c],
                         g_V[((size_t)(bb * 32 + y) * 32 + x) * 256 + c], accum);
        }
    }
    g_X[idx] += fmaf(g_spe[c], accum, g_bpe[c]);
}

// ---------------- GEMM 3: out = X(8192x256) @ Wp(256x256) + BN -------------
__global__ __launch_bounds__(256)
void proj_gemm(const float* __restrict__ W, float* __restrict__ out) {
    __shared__ float As[16][64];
    __shared__ float Bs[16][64];
    int tx = threadIdx.x, ty = threadIdx.y;
    int tid = ty * 16 + tx;
    int m0 = blockIdx.y * 64, n0 = blockIdx.x * 64;

    float acc[4][4] = {};
    int arow = tid >> 2, akq = (tid & 3) * 4;
    int brow = tid >> 4, bcol = (tid & 15) * 4;

    for (int k0 = 0; k0 < CDIM; k0 += 16) {
        float4 a4 = *(const float4*)&g_X[(size_t)(m0 + arow) * CDIM + k0 + akq];
        As[akq + 0][arow] = a4.x; As[akq + 1][arow] = a4.y;
        As[akq + 2][arow] = a4.z; As[akq + 3][arow] = a4.w;
        *(float4*)&Bs[brow][bcol] =
            *(const float4*)&W[(size_t)(k0 + brow) * CDIM + n0 + bcol];
        __syncthreads();
        #pragma unroll
        for (int kk = 0; kk < 16; kk++) {
            float4 av = *(float4*)&As[kk][ty * 4];
            float4 bv = *(float4*)&Bs[kk][tx * 4];
            float a[4] = {av.x, av.y, av.z, av.w};
            float b[4] = {bv.x, bv.y, bv.z, bv.w};
            #pragma unroll
            for (int i = 0; i < 4; i++)
                #pragma unroll
                for (int j = 0; j < 4; j++)
                    acc[i][j] = fmaf(a[i], b[j], acc[i][j]);
        }
        __syncthreads();
    }

    #pragma unroll
    for (int i = 0; i < 4; i++) {
        int gm = m0 + ty * 4 + i;
        #pragma unroll
        for (int j = 0; j < 4; j++) {
            int gn = n0 + tx * 4 + j;
            out[(size_t)gm * CDIM + gn] = fmaf(acc[i][j], g_sprj[gn], g_bprj[gn]);
        }
    }
}

// ---------------------------------------------------------------------------
extern "C" void kernel_launch(void* const* d_in, const int* in_sizes, int n_in,
                              void* d_out, int out_size) {
    const float* inp    = (const float*)d_in[0];
    const float* qkv_w  = (const float*)d_in[1];
    const float* pe_w   = (const float*)d_in[6];
    const float* proj_w = (const float*)d_in[11];

    cudaFuncSetAttribute(attn_softmax,
                         cudaFuncAttributeMaxDynamicSharedMemorySize,
                         NSP * KROW * (int)sizeof(float));

    bn_prep<<<1, 512>>>((const float*)d_in[2],  (const float*)d_in[3],
                        (const float*)d_in[4],  (const float*)d_in[5],
                        (const float*)d_in[7],  (const float*)d_in[8],
                        (const float*)d_in[9],  (const float*)d_in[10],
                        (const float*)d_in[12], (const float*)d_in[13],
                        (const float*)d_in[14], (const float*)d_in[15]);

    qkv_gemm<<<dim3(HQKV / 64, MTOT / 64), dim3(16, 16)>>>(inp, qkv_w);

    attn_softmax<<<dim3(NSP / 32, NHEADS_TOT), 256,
                   NSP * KROW * (int)sizeof(float)>>>();

    av_gemm<<<dim3(NSP / 128, NHEADS_TOT), dim3(32, 8)>>>();

    pe_add<<<MTOT * CDIM / 256, 256>>>(pe_w);

    proj_gemm<<<dim3(CDIM / 64, MTOT / 64), dim3(16, 16)>>>(proj_w, (float*)d_out);
}

// round 6
// speedup vs baseline: 2.1291x; 2.1291x over previous
#include <cuda_runtime.h>

// ---------------------------------------------------------------------------
// SimpleAttention: qkv 1x1 conv+BN -> per-head transposed attention ->
//                  + depthwise 3x3 conv+BN(v) -> proj 1x1 conv+BN
// B=8, Hs=Ws=32 (N=1024), C=256, heads=8, key_dim=16, head_dim=32
// ---------------------------------------------------------------------------

#define BATCH 8
#define NSP   1024
#define CDIM  256
#define HQKV  512
#define NH    8
#define KDIM  16
#define HD    32
#define NHEADS_TOT 64
#define MTOT  8192
#define ATT_SCALE 0.25f
#define BN_EPS 0.001f

// ------------------------------- scratch ----------------------------------
__device__ __align__(16) float g_Q [NHEADS_TOT * NSP * KDIM];
__device__ __align__(16) float g_Kt[NHEADS_TOT * NSP * KDIM];
__device__ __align__(16) float g_V [MTOT * CDIM];
__device__ __align__(16) float g_P [(size_t)NHEADS_TOT * NSP * NSP];
__device__ __align__(16) float g_PE[MTOT * CDIM];
__device__ __align__(16) float g_X [MTOT * CDIM];
__device__ float g_sqkv[HQKV], g_bqkv[HQKV];
__device__ float g_spe [CDIM], g_bpe [CDIM];
__device__ float g_sprj[CDIM], g_bprj[CDIM];

// -------------------------- BN fold (tiny) ---------------------------------
__global__ void bn_prep(const float* __restrict__ qg, const float* __restrict__ qb,
                        const float* __restrict__ qm, const float* __restrict__ qv,
                        const float* __restrict__ pg, const float* __restrict__ pb,
                        const float* __restrict__ pm, const float* __restrict__ pv,
                        const float* __restrict__ rg, const float* __restrict__ rb,
                        const float* __restrict__ rm, const float* __restrict__ rv) {
    int i = threadIdx.x;
    if (i < HQKV) {
        float s = qg[i] * rsqrtf(qv[i] + BN_EPS);
        g_sqkv[i] = s; g_bqkv[i] = qb[i] - qm[i] * s;
    }
    if (i < CDIM) {
        float s = pg[i] * rsqrtf(pv[i] + BN_EPS);
        g_spe[i] = s; g_bpe[i] = pb[i] - pm[i] * s;
        float s2 = rg[i] * rsqrtf(rv[i] + BN_EPS);
        g_sprj[i] = s2; g_bprj[i] = rb[i] - rm[i] * s2;
    }
}

// ---------------- GEMM 1: QKV = X(8192x256) @ W(256x512), BN, scatter ------
// 128x128 tile, 256 threads, 8x8 microtile (split 4+4 fragments).
__global__ __launch_bounds__(256)
void qkv_gemm(const float* __restrict__ A, const float* __restrict__ W) {
    __shared__ float As[16][128];
    __shared__ float Bs[16][128];
    int tid = threadIdx.x;
    int m0 = blockIdx.y * 128, n0 = blockIdx.x * 128;
    int tx = tid & 15, ty = tid >> 4;
    int ar = tid >> 2, ak = (tid & 3) * 4;
    int br = tid >> 5, bc = (tid & 31) * 4;

    float acc[8][8] = {};

    for (int k0 = 0; k0 < CDIM; k0 += 16) {
        #pragma unroll
        for (int it = 0; it < 2; it++) {
            float4 a4 = *(const float4*)&A[(size_t)(m0 + ar + it * 64) * CDIM + k0 + ak];
            As[ak + 0][ar + it * 64] = a4.x; As[ak + 1][ar + it * 64] = a4.y;
            As[ak + 2][ar + it * 64] = a4.z; As[ak + 3][ar + it * 64] = a4.w;
            *(float4*)&Bs[br + it * 8][bc] =
                *(const float4*)&W[(size_t)(k0 + br + it * 8) * HQKV + n0 + bc];
        }
        __syncthreads();
        #pragma unroll
        for (int kk = 0; kk < 16; kk++) {
            float4 a0 = *(float4*)&As[kk][ty * 4];
            float4 a1 = *(float4*)&As[kk][64 + ty * 4];
            float4 b0 = *(float4*)&Bs[kk][tx * 4];
            float4 b1 = *(float4*)&Bs[kk][64 + tx * 4];
            float am[8] = {a0.x, a0.y, a0.z, a0.w, a1.x, a1.y, a1.z, a1.w};
            float bn[8] = {b0.x, b0.y, b0.z, b0.w, b1.x, b1.y, b1.z, b1.w};
            #pragma unroll
            for (int i = 0; i < 8; i++)
                #pragma unroll
                for (int j = 0; j < 8; j++)
                    acc[i][j] = fmaf(am[i], bn[j], acc[i][j]);
        }
        __syncthreads();
    }

    #pragma unroll
    for (int mi = 0; mi < 8; mi++) {
        int gm = m0 + ((mi < 4) ? ty * 4 + mi : 64 + ty * 4 + mi - 4);
        int bb = gm >> 10, n = gm & 1023;
        #pragma unroll
        for (int ni = 0; ni < 8; ni++) {
            int gn = n0 + ((ni < 4) ? tx * 4 + ni : 64 + tx * 4 + ni - 4);
            float v = fmaf(acc[mi][ni], g_sqkv[gn], g_bqkv[gn]);
            int h = gn >> 6, r = gn & 63;
            if (r < KDIM)
                g_Q[((bb * NH + h) * NSP + n) * KDIM + r] = v;
            else if (r < 2 * KDIM)
                g_Kt[((bb * NH + h) * NSP + n) * KDIM + (r - KDIM)] = v;
            else
                g_V[(size_t)gm * CDIM + h * HD + (r - 2 * KDIM)] = v;
        }
    }
}

// ---------------- depthwise 3x3 conv on v_img + BN -> g_PE -----------------
__global__ __launch_bounds__(256)
void pe_conv(const float* __restrict__ pw) {
    int idx = blockIdx.x * 256 + threadIdx.x;
    int c  = idx & 255;
    int ws = (idx >> 8) & 31;
    int hs = (idx >> 13) & 31;
    int bb = idx >> 18;
    float accum = 0.f;
    #pragma unroll
    for (int dy = 0; dy < 3; dy++) {
        int y = hs + dy - 1;
        if ((unsigned)y >= 32u) continue;
        #pragma unroll
        for (int dx = 0; dx < 3; dx++) {
            int x = ws + dx - 1;
            if ((unsigned)x >= 32u) continue;
            accum = fmaf(pw[(dy * 3 + dx) * 256 + c],
                         g_V[((size_t)(bb * 32 + y) * 32 + x) * 256 + c], accum);
        }
    }
    g_PE[idx] = fmaf(g_spe[c], accum, g_bpe[c]);
}

// ---------------- Attention scores + softmax -> g_P ------------------------
// One block = 32 rows of one head; K resident in SMEM (stride-20 rows).
// ONE row per warp (low register pressure — spill-proof), 4 rows sequential.
#define KROW 20
__device__ __forceinline__ float dot16(float4 q0, float4 q1, float4 q2, float4 q3,
                                       const float* kp) {
    float4 k0 = *(const float4*)&kp[0];
    float4 k1 = *(const float4*)&kp[4];
    float4 k2 = *(const float4*)&kp[8];
    float4 k3 = *(const float4*)&kp[12];
    float d = q0.x * k0.x;
    d = fmaf(q0.y, k0.y, d); d = fmaf(q0.z, k0.z, d); d = fmaf(q0.w, k0.w, d);
    d = fmaf(q1.x, k1.x, d); d = fmaf(q1.y, k1.y, d); d = fmaf(q1.z, k1.z, d);
    d = fmaf(q1.w, k1.w, d); d = fmaf(q2.x, k2.x, d); d = fmaf(q2.y, k2.y, d);
    d = fmaf(q2.z, k2.z, d); d = fmaf(q2.w, k2.w, d); d = fmaf(q3.x, k3.x, d);
    d = fmaf(q3.y, k3.y, d); d = fmaf(q3.z, k3.z, d); d = fmaf(q3.w, k3.w, d);
    return d;
}

__global__ __launch_bounds__(256)
void attn_softmax() {
    extern __shared__ float Ks[];                 // [1024][KROW]
    int head = blockIdx.y;
    int tid = threadIdx.x;

    const float4* Kg = (const float4*)(g_Kt + (size_t)head * NSP * KDIM);
    for (int idx = tid; idx < NSP * 4; idx += 256) {
        int m = idx >> 2, q = idx & 3;
        *(float4*)&Ks[m * KROW + q * 4] = Kg[idx];
    }
    __syncthreads();

    int warp = tid >> 5, lane = tid & 31;
    for (int rr = 0; rr < 4; rr++) {
        int row = blockIdx.x * 32 + warp * 4 + rr;
        const float* qp = g_Q + ((size_t)head * NSP + row) * KDIM;
        float4 q0 = *(const float4*)&qp[0], q1 = *(const float4*)&qp[4];
        float4 q2 = *(const float4*)&qp[8], q3 = *(const float4*)&qp[12];

        float s[32];
        float mx = -1e30f;
        #pragma unroll
        for (int i = 0; i < 32; i++) {
            s[i] = dot16(q0, q1, q2, q3, &Ks[(i * 32 + lane) * KROW]) * ATT_SCALE;
            mx = fmaxf(mx, s[i]);
        }
        #pragma unroll
        for (int o = 16; o > 0; o >>= 1)
            mx = fmaxf(mx, __shfl_xor_sync(0xffffffffu, mx, o));
        float sum = 0.f;
        #pragma unroll
        for (int i = 0; i < 32; i++) {
            s[i] = __expf(s[i] - mx);
            sum += s[i];
        }
        #pragma unroll
        for (int o = 16; o > 0; o >>= 1)
            sum += __shfl_xor_sync(0xffffffffu, sum, o);
        float inv = 1.f / sum;
        float* Pr = g_P + (size_t)head * NSP * NSP + (size_t)row * NSP;
        #pragma unroll
        for (int i = 0; i < 32; i++)
            Pr[i * 32 + lane] = s[i] * inv;
    }
}

// ---------------- out[m,d] = sum_n P[n,m] * V[n,d]; += PE -> g_X -----------
// Per head: 128m x 32d tile, 64 threads, 8x8 microtile (1 B/FMA LDS ratio).
__global__ __launch_bounds__(64)
void av_gemm() {
    __shared__ float Ps[32][128];
    __shared__ float Vs[32][32];
    int head = blockIdx.y;
    int bb = head >> 3, h = head & 7;
    int m0 = blockIdx.x * 128;
    int tid = threadIdx.x;
    int tm = tid >> 2, tx = tid & 3;

    const float* Pb = g_P + (size_t)head * NSP * NSP;
    const float* Vb = g_V + (size_t)bb * NSP * CDIM + h * HD;

    float acc[8][8] = {};

    for (int n0 = 0; n0 < NSP; n0 += 32) {
        #pragma unroll
        for (int j = 0; j < 16; j++) {
            int fi = tid + j * 64;              // 0..1023
            int r = fi >> 5, c4 = (fi & 31) * 4;
            *(float4*)&Ps[r][c4] = *(const float4*)&Pb[(size_t)(n0 + r) * NSP + m0 + c4];
        }
        #pragma unroll
        for (int j = 0; j < 4; j++) {
            int fi = tid + j * 64;              // 0..255
            int r = fi >> 3, c4 = (fi & 7) * 4;
            *(float4*)&Vs[r][c4] = *(const float4*)&Vb[(size_t)(n0 + r) * CDIM + c4];
        }
        __syncthreads();
        #pragma unroll
        for (int kk = 0; kk < 32; kk++) {
            float4 p0 = *(float4*)&Ps[kk][tm * 4];
            float4 p1 = *(float4*)&Ps[kk][64 + tm * 4];
            float4 v0 = *(float4*)&Vs[kk][tx * 4];
            float4 v1 = *(float4*)&Vs[kk][16 + tx * 4];
            float pm[8] = {p0.x, p0.y, p0.z, p0.w, p1.x, p1.y, p1.z, p1.w};
            float vd[8] = {v0.x, v0.y, v0.z, v0.w, v1.x, v1.y, v1.z, v1.w};
            #pragma unroll
            for (int i = 0; i < 8; i++)
                #pragma unroll
                for (int j = 0; j < 8; j++)
                    acc[i][j] = fmaf(pm[i], vd[j], acc[i][j]);
        }
        __syncthreads();
    }

    // x_img[b, hs=d, ws=h*4+(m>>8), c=m&255] = attn_out[m,d] + pe
    int ws = h * 4 + (m0 >> 8);
    int cbase = (m0 & 255) + tm * 4;
    #pragma unroll
    for (int dj = 0; dj < 8; dj++) {
        int d = (dj < 4) ? tx * 4 + dj : 16 + tx * 4 + dj - 4;
        size_t rowb = ((size_t)(bb * 32 + d) * 32 + ws) * CDIM;
        float4 pe0 = *(const float4*)&g_PE[rowb + cbase];
        float4 pe1 = *(const float4*)&g_PE[rowb + cbase + 64];
        float4 o0 = {acc[0][dj] + pe0.x, acc[1][dj] + pe0.y,
                     acc[2][dj] + pe0.z, acc[3][dj] + pe0.w};
        float4 o1 = {acc[4][dj] + pe1.x, acc[5][dj] + pe1.y,
                     acc[6][dj] + pe1.z, acc[7][dj] + pe1.w};
        *(float4*)&g_X[rowb + cbase]      = o0;
        *(float4*)&g_X[rowb + cbase + 64] = o1;
    }
}

// ---------------- GEMM 3: out = X(8192x256) @ Wp(256x256) + BN -------------
__global__ __launch_bounds__(256)
void proj_gemm(const float* __restrict__ W, float* __restrict__ out) {
    __shared__ float As[16][128];
    __shared__ float Bs[16][128];
    int tid = threadIdx.x;
    int m0 = blockIdx.y * 128, n0 = blockIdx.x * 128;
    int tx = tid & 15, ty = tid >> 4;
    int ar = tid >> 2, ak = (tid & 3) * 4;
    int br = tid >> 5, bc = (tid & 31) * 4;

    float acc[8][8] = {};

    for (int k0 = 0; k0 < CDIM; k0 += 16) {
        #pragma unroll
        for (int it = 0; it < 2; it++) {
            float4 a4 = *(const float4*)&g_X[(size_t)(m0 + ar + it * 64) * CDIM + k0 + ak];
            As[ak + 0][ar + it * 64] = a4.x; As[ak + 1][ar + it * 64] = a4.y;
            As[ak + 2][ar + it * 64] = a4.z; As[ak + 3][ar + it * 64] = a4.w;
            *(float4*)&Bs[br + it * 8][bc] =
                *(const float4*)&W[(size_t)(k0 + br + it * 8) * CDIM + n0 + bc];
        }
        __syncthreads();
        #pragma unroll
        for (int kk = 0; kk < 16; kk++) {
            float4 a0 = *(float4*)&As[kk][ty * 4];
            float4 a1 = *(float4*)&As[kk][64 + ty * 4];
            float4 b0 = *(float4*)&Bs[kk][tx * 4];
            float4 b1 = *(float4*)&Bs[kk][64 + tx * 4];
            float am[8] = {a0.x, a0.y, a0.z, a0.w, a1.x, a1.y, a1.z, a1.w};
            float bn[8] = {b0.x, b0.y, b0.z, b0.w, b1.x, b1.y, b1.z, b1.w};
            #pragma unroll
            for (int i = 0; i < 8; i++)
                #pragma unroll
                for (int j = 0; j < 8; j++)
                    acc[i][j] = fmaf(am[i], bn[j], acc[i][j]);
        }
        __syncthreads();
    }

    #pragma unroll
    for (int mi = 0; mi < 8; mi++) {
        int gm = m0 + ((mi < 4) ? ty * 4 + mi : 64 + ty * 4 + mi - 4);
        #pragma unroll
        for (int fr = 0; fr < 2; fr++) {
            int gnb = n0 + fr * 64 + tx * 4;
            float4 o;
            o.x = fmaf(acc[mi][fr * 4 + 0], g_sprj[gnb + 0], g_bprj[gnb + 0]);
            o.y = fmaf(acc[mi][fr * 4 + 1], g_sprj[gnb + 1], g_bprj[gnb + 1]);
            o.z = fmaf(acc[mi][fr * 4 + 2], g_sprj[gnb + 2], g_bprj[gnb + 2]);
            o.w = fmaf(acc[mi][fr * 4 + 3], g_sprj[gnb + 3], g_bprj[gnb + 3]);
            *(float4*)&out[(size_t)gm * CDIM + gnb] = o;
        }
    }
}

// ---------------------------------------------------------------------------
extern "C" void kernel_launch(void* const* d_in, const int* in_sizes, int n_in,
                              void* d_out, int out_size) {
    const float* inp    = (const float*)d_in[0];
    const float* qkv_w  = (const float*)d_in[1];
    const float* pe_w   = (const float*)d_in[6];
    const float* proj_w = (const float*)d_in[11];

    cudaFuncSetAttribute(attn_softmax,
                         cudaFuncAttributeMaxDynamicSharedMemorySize,
                         NSP * KROW * (int)sizeof(float));

    bn_prep<<<1, 512>>>((const float*)d_in[2],  (const float*)d_in[3],
                        (const float*)d_in[4],  (const float*)d_in[5],
                        (const float*)d_in[7],  (const float*)d_in[8],
                        (const float*)d_in[9],  (const float*)d_in[10],
                        (const float*)d_in[12], (const float*)d_in[13],
                        (const float*)d_in[14], (const float*)d_in[15]);

    qkv_gemm<<<dim3(HQKV / 128, MTOT / 128), 256>>>(inp, qkv_w);

    // pe before softmax: puts attn_softmax into the ncu capture slot (#6)
    pe_conv<<<MTOT * CDIM / 256, 256>>>(pe_w);

    attn_softmax<<<dim3(NSP / 32, NHEADS_TOT), 256,
                   NSP * KROW * (int)sizeof(float)>>>();

    av_gemm<<<dim3(NSP / 128, NHEADS_TOT), 64>>>();

    proj_gemm<<<dim3(CDIM / 128, MTOT / 128), 256>>>(proj_w, (float*)d_out);
}

// round 7
// speedup vs baseline: 2.8561x; 1.3414x over previous
#include <cuda_runtime.h>

// ---------------------------------------------------------------------------
// SimpleAttention: qkv 1x1 conv+BN -> per-head transposed attention ->
//                  + depthwise 3x3 conv+BN(v) -> proj 1x1 conv+BN
// B=8, Hs=Ws=32 (N=1024), C=256, heads=8, key_dim=16, head_dim=32
// ---------------------------------------------------------------------------

#define BATCH 8
#define NSP   1024
#define CDIM  256
#define HQKV  512
#define NH    8
#define KDIM  16
#define HD    32
#define NHEADS_TOT 64
#define MTOT  8192
#define ATT_SCALE 0.25f
#define BN_EPS 0.001f

// ------------------------------- scratch ----------------------------------
__device__ __align__(16) float g_Q [NHEADS_TOT * NSP * KDIM];
__device__ __align__(16) float g_Kt[NHEADS_TOT * NSP * KDIM];
__device__ __align__(16) float g_V [MTOT * CDIM];
__device__ __align__(16) float g_P [(size_t)NHEADS_TOT * NSP * NSP];
__device__ __align__(16) float g_PE[MTOT * CDIM];
__device__ __align__(16) float g_X [MTOT * CDIM];

// ---------------- fast exp: FFMA-only (no MUFU) ----------------------------
// exp(x) = 2^(x*log2e); n = round(t) via magic add, 2^f by deg-6 Taylor.
// Valid for x in [-80, 0]; |rel err| ~1e-7.
__device__ __forceinline__ float fexp(float x) {
    const float L2E = 1.4426950408889634f;
    float t = x * L2E;
    float z = t + 12582912.0f;                     // round-to-nearest int
    int   e = __float_as_int(z) << 23;             // n in exponent position
    float f = t - (z - 12582912.0f);               // f in [-0.5, 0.5]
    float p = 1.5403530e-4f;
    p = fmaf(p, f, 1.3333558e-3f);
    p = fmaf(p, f, 9.6181291e-3f);
    p = fmaf(p, f, 5.5504109e-2f);
    p = fmaf(p, f, 2.4022651e-1f);
    p = fmaf(p, f, 6.9314718e-1f);
    p = fmaf(p, f, 1.0f);
    return __int_as_float(__float_as_int(p) + e);
}

// ---------------- GEMM 1: QKV = X(8192x256) @ W(256x512), BN, scatter ------
// 128x128 tile, 256 threads, 8x8 microtile (split 4+4 fragments).
__global__ __launch_bounds__(256)
void qkv_gemm(const float* __restrict__ A, const float* __restrict__ W,
              const float* __restrict__ qg, const float* __restrict__ qb,
              const float* __restrict__ qm, const float* __restrict__ qv) {
    __shared__ float As[16][128];
    __shared__ float Bs[16][128];
    int tid = threadIdx.x;
    int m0 = blockIdx.y * 128, n0 = blockIdx.x * 128;
    int tx = tid & 15, ty = tid >> 4;
    int ar = tid >> 2, ak = (tid & 3) * 4;
    int br = tid >> 5, bc = (tid & 31) * 4;

    float acc[8][8] = {};

    for (int k0 = 0; k0 < CDIM; k0 += 16) {
        #pragma unroll
        for (int it = 0; it < 2; it++) {
            float4 a4 = *(const float4*)&A[(size_t)(m0 + ar + it * 64) * CDIM + k0 + ak];
            As[ak + 0][ar + it * 64] = a4.x; As[ak + 1][ar + it * 64] = a4.y;
            As[ak + 2][ar + it * 64] = a4.z; As[ak + 3][ar + it * 64] = a4.w;
            *(float4*)&Bs[br + it * 8][bc] =
                *(const float4*)&W[(size_t)(k0 + br + it * 8) * HQKV + n0 + bc];
        }
        __syncthreads();
        #pragma unroll
        for (int kk = 0; kk < 16; kk++) {
            float4 a0 = *(float4*)&As[kk][ty * 4];
            float4 a1 = *(float4*)&As[kk][64 + ty * 4];
            float4 b0 = *(float4*)&Bs[kk][tx * 4];
            float4 b1 = *(float4*)&Bs[kk][64 + tx * 4];
            float am[8] = {a0.x, a0.y, a0.z, a0.w, a1.x, a1.y, a1.z, a1.w};
            float bn[8] = {b0.x, b0.y, b0.z, b0.w, b1.x, b1.y, b1.z, b1.w};
            #pragma unroll
            for (int i = 0; i < 8; i++)
                #pragma unroll
                for (int j = 0; j < 8; j++)
                    acc[i][j] = fmaf(am[i], bn[j], acc[i][j]);
        }
        __syncthreads();
    }

    // inline BN fold for the 8 output columns this thread owns
    float sc[8], bs[8];
    int gncol[8];
    #pragma unroll
    for (int ni = 0; ni < 8; ni++) {
        int gn = n0 + ((ni < 4) ? tx * 4 + ni : 64 + tx * 4 + ni - 4);
        gncol[ni] = gn;
        float s = qg[gn] * rsqrtf(qv[gn] + BN_EPS);
        sc[ni] = s; bs[ni] = qb[gn] - qm[gn] * s;
    }

    #pragma unroll
    for (int mi = 0; mi < 8; mi++) {
        int gm = m0 + ((mi < 4) ? ty * 4 + mi : 64 + ty * 4 + mi - 4);
        int bb = gm >> 10, n = gm & 1023;
        #pragma unroll
        for (int ni = 0; ni < 8; ni++) {
            int gn = gncol[ni];
            float v = fmaf(acc[mi][ni], sc[ni], bs[ni]);
            int h = gn >> 6, r = gn & 63;
            if (r < KDIM)
                g_Q[((bb * NH + h) * NSP + n) * KDIM + r] = v;
            else if (r < 2 * KDIM)
                g_Kt[((bb * NH + h) * NSP + n) * KDIM + (r - KDIM)] = v;
            else
                g_V[(size_t)gm * CDIM + h * HD + (r - 2 * KDIM)] = v;
        }
    }
}

// ---------------- Attention scores + softmax -> g_P ------------------------
// One block = 64 rows of one head; K resident in SMEM (stride-20 rows: the
// float4 phase pattern covers all 32 banks -> conflict-free).
// 128 threads; each warp processes 2 rows concurrently (halves LDS traffic),
// 8 pairs sequential. exp is FFMA-only (fexp).
#define KROW 20
__device__ __forceinline__ float dot16(float4 q0, float4 q1, float4 q2, float4 q3,
                                       const float* kp) {
    float4 k0 = *(const float4*)&kp[0];
    float4 k1 = *(const float4*)&kp[4];
    float4 k2 = *(const float4*)&kp[8];
    float4 k3 = *(const float4*)&kp[12];
    float d = q0.x * k0.x;
    d = fmaf(q0.y, k0.y, d); d = fmaf(q0.z, k0.z, d); d = fmaf(q0.w, k0.w, d);
    d = fmaf(q1.x, k1.x, d); d = fmaf(q1.y, k1.y, d); d = fmaf(q1.z, k1.z, d);
    d = fmaf(q1.w, k1.w, d); d = fmaf(q2.x, k2.x, d); d = fmaf(q2.y, k2.y, d);
    d = fmaf(q2.z, k2.z, d); d = fmaf(q2.w, k2.w, d); d = fmaf(q3.x, k3.x, d);
    d = fmaf(q3.y, k3.y, d); d = fmaf(q3.z, k3.z, d); d = fmaf(q3.w, k3.w, d);
    return d;
}

__global__ __launch_bounds__(128)
void attn_softmax() {
    extern __shared__ float Ks[];                 // [1024][KROW]
    int head = blockIdx.y;
    int tid = threadIdx.x;

    const float4* Kg = (const float4*)(g_Kt + (size_t)head * NSP * KDIM);
    for (int idx = tid; idx < NSP * 4; idx += 128) {
        int m = idx >> 2, q = idx & 3;
        *(float4*)&Ks[m * KROW + q * 4] = Kg[idx];
    }
    __syncthreads();

    int warp = tid >> 5, lane = tid & 31;
    for (int pair = 0; pair < 8; pair++) {
        int rowA = blockIdx.x * 64 + warp * 16 + pair * 2;
        int rowB = rowA + 1;
        const float* qa = g_Q + ((size_t)head * NSP + rowA) * KDIM;
        const float* qb = g_Q + ((size_t)head * NSP + rowB) * KDIM;
        float4 qa0 = *(const float4*)&qa[0], qa1 = *(const float4*)&qa[4];
        float4 qa2 = *(const float4*)&qa[8], qa3 = *(const float4*)&qa[12];
        float4 qb0 = *(const float4*)&qb[0], qb1 = *(const float4*)&qb[4];
        float4 qb2 = *(const float4*)&qb[8], qb3 = *(const float4*)&qb[12];

        float sA[32], sB[32];
        float mxA = -1e30f, mxB = -1e30f;
        #pragma unroll
        for (int i = 0; i < 32; i++) {
            const float* kp = &Ks[(i * 32 + lane) * KROW];
            float dA = dot16(qa0, qa1, qa2, qa3, kp);
            float dB = dot16(qb0, qb1, qb2, qb3, kp);
            sA[i] = dA * ATT_SCALE; sB[i] = dB * ATT_SCALE;
            mxA = fmaxf(mxA, sA[i]); mxB = fmaxf(mxB, sB[i]);
        }
        #pragma unroll
        for (int o = 16; o > 0; o >>= 1) {
            mxA = fmaxf(mxA, __shfl_xor_sync(0xffffffffu, mxA, o));
            mxB = fmaxf(mxB, __shfl_xor_sync(0xffffffffu, mxB, o));
        }
        float sumA = 0.f, sumB = 0.f;
        #pragma unroll
        for (int i = 0; i < 32; i++) {
            sA[i] = fexp(fmaxf(sA[i] - mxA, -80.f)); sumA += sA[i];
            sB[i] = fexp(fmaxf(sB[i] - mxB, -80.f)); sumB += sB[i];
        }
        #pragma unroll
        for (int o = 16; o > 0; o >>= 1) {
            sumA += __shfl_xor_sync(0xffffffffu, sumA, o);
            sumB += __shfl_xor_sync(0xffffffffu, sumB, o);
        }
        float invA = 1.f / sumA, invB = 1.f / sumB;
        float* PrA = g_P + (size_t)head * NSP * NSP + (size_t)rowA * NSP;
        float* PrB = g_P + (size_t)head * NSP * NSP + (size_t)rowB * NSP;
        #pragma unroll
        for (int i = 0; i < 32; i++) {
            PrA[i * 32 + lane] = sA[i] * invA;
            PrB[i * 32 + lane] = sB[i] * invB;
        }
    }
}

// ---------------- depthwise 3x3 conv on v_img + BN -> g_PE -----------------
__global__ __launch_bounds__(256)
void pe_conv(const float* __restrict__ pw,
             const float* __restrict__ pg, const float* __restrict__ pb,
             const float* __restrict__ pm, const float* __restrict__ pv) {
    int idx = blockIdx.x * 256 + threadIdx.x;
    int c  = idx & 255;
    int ws = (idx >> 8) & 31;
    int hs = (idx >> 13) & 31;
    int bb = idx >> 18;
    float accum = 0.f;
    #pragma unroll
    for (int dy = 0; dy < 3; dy++) {
        int y = hs + dy - 1;
        if ((unsigned)y >= 32u) continue;
        #pragma unroll
        for (int dx = 0; dx < 3; dx++) {
            int x = ws + dx - 1;
            if ((unsigned)x >= 32u) continue;
            accum = fmaf(pw[(dy * 3 + dx) * 256 + c],
                         g_V[((size_t)(bb * 32 + y) * 32 + x) * 256 + c], accum);
        }
    }
    float s = pg[c] * rsqrtf(pv[c] + BN_EPS);
    g_PE[idx] = fmaf(s, accum, pb[c] - pm[c] * s);
}

// ---------------- out[m,d] = sum_n P[n,m] * V[n,d]; += PE -> g_X -----------
// Per head: 128m x 32d tile, 64 threads, 8x8 microtile (1 B/FMA LDS ratio).
__global__ __launch_bounds__(64)
void av_gemm() {
    __shared__ float Ps[32][128];
    __shared__ float Vs[32][32];
    int head = blockIdx.y;
    int bb = head >> 3, h = head & 7;
    int m0 = blockIdx.x * 128;
    int tid = threadIdx.x;
    int tm = tid >> 2, tx = tid & 3;

    const float* Pb = g_P + (size_t)head * NSP * NSP;
    const float* Vb = g_V + (size_t)bb * NSP * CDIM + h * HD;

    float acc[8][8] = {};

    for (int n0 = 0; n0 < NSP; n0 += 32) {
        #pragma unroll
        for (int j = 0; j < 16; j++) {
            int fi = tid + j * 64;
            int r = fi >> 5, c4 = (fi & 31) * 4;
            *(float4*)&Ps[r][c4] = *(const float4*)&Pb[(size_t)(n0 + r) * NSP + m0 + c4];
        }
        #pragma unroll
        for (int j = 0; j < 4; j++) {
            int fi = tid + j * 64;
            int r = fi >> 3, c4 = (fi & 7) * 4;
            *(float4*)&Vs[r][c4] = *(const float4*)&Vb[(size_t)(n0 + r) * CDIM + c4];
        }
        __syncthreads();
        #pragma unroll
        for (int kk = 0; kk < 32; kk++) {
            float4 p0 = *(float4*)&Ps[kk][tm * 4];
            float4 p1 = *(float4*)&Ps[kk][64 + tm * 4];
            float4 v0 = *(float4*)&Vs[kk][tx * 4];
            float4 v1 = *(float4*)&Vs[kk][16 + tx * 4];
            float pm[8] = {p0.x, p0.y, p0.z, p0.w, p1.x, p1.y, p1.z, p1.w};
            float vd[8] = {v0.x, v0.y, v0.z, v0.w, v1.x, v1.y, v1.z, v1.w};
            #pragma unroll
            for (int i = 0; i < 8; i++)
                #pragma unroll
                for (int j = 0; j < 8; j++)
                    acc[i][j] = fmaf(pm[i], vd[j], acc[i][j]);
        }
        __syncthreads();
    }

    // x_img[b, hs=d, ws=h*4+(m>>8), c=m&255] = attn_out[m,d] + pe
    int ws = h * 4 + (m0 >> 8);
    int cbase = (m0 & 255) + tm * 4;
    #pragma unroll
    for (int dj = 0; dj < 8; dj++) {
        int d = (dj < 4) ? tx * 4 + dj : 16 + tx * 4 + dj - 4;
        size_t rowb = ((size_t)(bb * 32 + d) * 32 + ws) * CDIM;
        float4 pe0 = *(const float4*)&g_PE[rowb + cbase];
        float4 pe1 = *(const float4*)&g_PE[rowb + cbase + 64];
        float4 o0 = {acc[0][dj] + pe0.x, acc[1][dj] + pe0.y,
                     acc[2][dj] + pe0.z, acc[3][dj] + pe0.w};
        float4 o1 = {acc[4][dj] + pe1.x, acc[5][dj] + pe1.y,
                     acc[6][dj] + pe1.z, acc[7][dj] + pe1.w};
        *(float4*)&g_X[rowb + cbase]      = o0;
        *(float4*)&g_X[rowb + cbase + 64] = o1;
    }
}

// ---------------- GEMM 3: out = X(8192x256) @ Wp(256x256) + BN -------------
__global__ __launch_bounds__(256)
void proj_gemm(const float* __restrict__ W, float* __restrict__ out,
               const float* __restrict__ rg, const float* __restrict__ rb,
               const float* __restrict__ rm, const float* __restrict__ rv) {
    __shared__ float As[16][128];
    __shared__ float Bs[16][128];
    int tid = threadIdx.x;
    int m0 = blockIdx.y * 128, n0 = blockIdx.x * 128;
    int tx = tid & 15, ty = tid >> 4;
    int ar = tid >> 2, ak = (tid & 3) * 4;
    int br = tid >> 5, bc = (tid & 31) * 4;

    float acc[8][8] = {};

    for (int k0 = 0; k0 < CDIM; k0 += 16) {
        #pragma unroll
        for (int it = 0; it < 2; it++) {
            float4 a4 = *(const float4*)&g_X[(size_t)(m0 + ar + it * 64) * CDIM + k0 + ak];
            As[ak + 0][ar + it * 64] = a4.x; As[ak + 1][ar + it * 64] = a4.y;
            As[ak + 2][ar + it * 64] = a4.z; As[ak + 3][ar + it * 64] = a4.w;
            *(float4*)&Bs[br + it * 8][bc] =
                *(const float4*)&W[(size_t)(k0 + br + it * 8) * CDIM + n0 + bc];
        }
        __syncthreads();
        #pragma unroll
        for (int kk = 0; kk < 16; kk++) {
            float4 a0 = *(float4*)&As[kk][ty * 4];
            float4 a1 = *(float4*)&As[kk][64 + ty * 4];
            float4 b0 = *(float4*)&Bs[kk][tx * 4];
            float4 b1 = *(float4*)&Bs[kk][64 + tx * 4];
            float am[8] = {a0.x, a0.y, a0.z, a0.w, a1.x, a1.y, a1.z, a1.w};
            float bn[8] = {b0.x, b0.y, b0.z, b0.w, b1.x, b1.y, b1.z, b1.w};
            #pragma unroll
            for (int i = 0; i < 8; i++)
                #pragma unroll
                for (int j = 0; j < 8; j++)
                    acc[i][j] = fmaf(am[i], bn[j], acc[i][j]);
        }
        __syncthreads();
    }

    // inline BN fold: vector loads of the 2x4 channel params this thread owns
    float sc[8], bs[8];
    #pragma unroll
    for (int fr = 0; fr < 2; fr++) {
        int gnb = n0 + fr * 64 + tx * 4;
        float4 g4 = *(const float4*)&rg[gnb];
        float4 b4 = *(const float4*)&rb[gnb];
        float4 m4 = *(const float4*)&rm[gnb];
        float4 v4 = *(const float4*)&rv[gnb];
        float gg[4] = {g4.x, g4.y, g4.z, g4.w};
        float bbv[4] = {b4.x, b4.y, b4.z, b4.w};
        float mm[4] = {m4.x, m4.y, m4.z, m4.w};
        float vv[4] = {v4.x, v4.y, v4.z, v4.w};
        #pragma unroll
        for (int j = 0; j < 4; j++) {
            float s = gg[j] * rsqrtf(vv[j] + BN_EPS);
            sc[fr * 4 + j] = s; bs[fr * 4 + j] = bbv[j] - mm[j] * s;
        }
    }

    #pragma unroll
    for (int mi = 0; mi < 8; mi++) {
        int gm = m0 + ((mi < 4) ? ty * 4 + mi : 64 + ty * 4 + mi - 4);
        #pragma unroll
        for (int fr = 0; fr < 2; fr++) {
            int gnb = n0 + fr * 64 + tx * 4;
            float4 o;
            o.x = fmaf(acc[mi][fr * 4 + 0], sc[fr * 4 + 0], bs[fr * 4 + 0]);
            o.y = fmaf(acc[mi][fr * 4 + 1], sc[fr * 4 + 1], bs[fr * 4 + 1]);
            o.z = fmaf(acc[mi][fr * 4 + 2], sc[fr * 4 + 2], bs[fr * 4 + 2]);
            o.w = fmaf(acc[mi][fr * 4 + 3], sc[fr * 4 + 3], bs[fr * 4 + 3]);
            *(float4*)&out[(size_t)gm * CDIM + gnb] = o;
        }
    }
}

// ---------------------------------------------------------------------------
extern "C" void kernel_launch(void* const* d_in, const int* in_sizes, int n_in,
                              void* d_out, int out_size) {
    const float* inp    = (const float*)d_in[0];
    const float* qkv_w  = (const float*)d_in[1];
    const float* pe_w   = (const float*)d_in[6];
    const float* proj_w = (const float*)d_in[11];

    cudaFuncSetAttribute(attn_softmax,
                         cudaFuncAttributeMaxDynamicSharedMemorySize,
                         NSP * KROW * (int)sizeof(float));

    // launch order: qkv(1) -> softmax(2) -> pe(3) -> av(4: ncu slot) -> proj(5)
    qkv_gemm<<<dim3(HQKV / 128, MTOT / 128), 256>>>(
        inp, qkv_w,
        (const float*)d_in[2], (const float*)d_in[3],
        (const float*)d_in[4], (const float*)d_in[5]);

    attn_softmax<<<dim3(NSP / 64, NHEADS_TOT), 128,
                   NSP * KROW * (int)sizeof(float)>>>();

    pe_conv<<<MTOT * CDIM / 256, 256>>>(
        pe_w,
        (const float*)d_in[7], (const float*)d_in[8],
        (const float*)d_in[9], (const float*)d_in[10]);

    av_gemm<<<dim3(NSP / 128, NHEADS_TOT), 64>>>();

    proj_gemm<<<dim3(CDIM / 128, MTOT / 128), 256>>>(
        proj_w, (float*)d_out,
        (const float*)d_in[12], (const float*)d_in[13],
        (const float*)d_in[14], (const float*)d_in[15]);
}